// round 1
// baseline (speedup 1.0000x reference)
#include <cuda_runtime.h>
#include <math.h>

#define T_TOK 8192
#define D_DIM 1024
#define H_DIM 2048
#define NE    8

// ---- static device scratch (no allocations allowed) ----
__device__ int   g_cnt[NE];
__device__ float g_imp[NE];
__device__ int   g_btok[NE * T_TOK];
__device__ float g_bw[NE * T_TOK];
__device__ float g_h[(size_t)NE * T_TOK * H_DIM];   // 512 MB worst-case hidden scratch

// ---------------------------------------------------------------------------
// zero output + counters
// ---------------------------------------------------------------------------
__global__ void zero_kernel(float* __restrict__ out) {
    size_t n4 = (size_t)T_TOK * D_DIM / 4;
    size_t i  = (size_t)blockIdx.x * blockDim.x + threadIdx.x;
    float4 z = make_float4(0.f, 0.f, 0.f, 0.f);
    for (; i < n4; i += (size_t)gridDim.x * blockDim.x)
        reinterpret_cast<float4*>(out)[i] = z;
    if (blockIdx.x == 0 && threadIdx.x < NE) {
        g_cnt[threadIdx.x] = 0;
        g_imp[threadIdx.x] = 0.f;
    }
}

// ---------------------------------------------------------------------------
// router: one warp per token
// ---------------------------------------------------------------------------
__global__ __launch_bounds__(256) void router_kernel(
    const float* __restrict__ x,
    const float* __restrict__ Wr,
    const float* __restrict__ br)
{
    __shared__ float sWr[D_DIM * NE];   // 32 KB
    __shared__ float s_imp[NE];
    int tid = threadIdx.x;
    for (int i = tid; i < D_DIM * NE; i += 256) sWr[i] = Wr[i];
    if (tid < NE) s_imp[tid] = 0.f;
    __syncthreads();

    int warp = tid >> 5, lane = tid & 31;
    int t = blockIdx.x * 8 + warp;

    float acc[NE];
#pragma unroll
    for (int e = 0; e < NE; e++) acc[e] = 0.f;

    const float* xr = x + (size_t)t * D_DIM;
    for (int d = lane; d < D_DIM; d += 32) {
        float xv = xr[d];
#pragma unroll
        for (int e = 0; e < NE; e++) acc[e] += xv * sWr[d * NE + e];
    }
#pragma unroll
    for (int e = 0; e < NE; e++) {
#pragma unroll
        for (int off = 16; off > 0; off >>= 1)
            acc[e] += __shfl_down_sync(0xffffffffu, acc[e], off);
    }

    if (lane == 0) {
        float p[NE];
        float mx = -1e30f;
#pragma unroll
        for (int e = 0; e < NE; e++) { p[e] = acc[e] + br[e]; mx = fmaxf(mx, p[e]); }
        float s = 0.f;
#pragma unroll
        for (int e = 0; e < NE; e++) { p[e] = expf(p[e] - mx); s += p[e]; }
        float inv = 1.f / s;
#pragma unroll
        for (int e = 0; e < NE; e++) {
            p[e] *= inv;
            atomicAdd(&s_imp[e], p[e]);
        }
        // top-2 (first index wins on ties, matching jax top_k)
        int i0 = 0;
#pragma unroll
        for (int e = 1; e < NE; e++) if (p[e] > p[i0]) i0 = e;
        int i1 = (i0 == 0) ? 1 : 0;
#pragma unroll
        for (int e = 0; e < NE; e++) if (e != i0 && p[e] > p[i1] && e != i1) {
            if (e < i1 || p[e] > p[i1]) i1 = e;
        }
        // (re-scan cleanly to be safe)
        i1 = -1;
        float best1 = -1.f;
#pragma unroll
        for (int e = 0; e < NE; e++) {
            if (e == i0) continue;
            if (p[e] > best1) { best1 = p[e]; i1 = e; }
        }
        float w0 = p[i0], w1 = p[i1];
        float ws = fmaxf(w0 + w1, 1e-9f);
        w0 /= ws; w1 /= ws;

        int s0 = atomicAdd(&g_cnt[i0], 1);
        g_btok[i0 * T_TOK + s0] = t;
        g_bw[i0 * T_TOK + s0]   = w0;
        int s1 = atomicAdd(&g_cnt[i1], 1);
        g_btok[i1 * T_TOK + s1] = t;
        g_bw[i1 * T_TOK + s1]   = w1;
    }
    __syncthreads();
    if (tid < NE) atomicAdd(&g_imp[tid], s_imp[tid]);
}

// ---------------------------------------------------------------------------
// GEMM1: gathered X[n_e, D] @ W1[e][D, H] -> gelu -> g_h
// 128x128 tile, BK=8, 256 threads, 8x8 microtile
// ---------------------------------------------------------------------------
__device__ __forceinline__ float gelu_exact(float v) {
    return 0.5f * v * (1.f + erff(v * 0.70710678118654752f));
}

__global__ __launch_bounds__(256) void gemm1_kernel(
    const float* __restrict__ x,
    const float* __restrict__ W1,
    const float* __restrict__ b1)
{
    int e   = blockIdx.z;
    int cnt = g_cnt[e];
    int row0 = blockIdx.y * 128;
    if (row0 >= cnt) return;
    int col0 = blockIdx.x * 128;

    __shared__ float As[8][128];
    __shared__ float Bs[8][128];
    __shared__ int   stok[128];

    int tid = threadIdx.x;
    if (tid < 128) {
        int r = row0 + tid;
        stok[tid] = (r < cnt) ? g_btok[e * T_TOK + r] : -1;
    }
    __syncthreads();

    int tx = tid & 15, ty = tid >> 4;
    float acc[8][8];
#pragma unroll
    for (int i = 0; i < 8; i++)
#pragma unroll
        for (int j = 0; j < 8; j++) acc[i][j] = 0.f;

    const float* Wb = W1 + (size_t)e * D_DIM * H_DIM;

    int arow = tid >> 1;
    int akq  = (tid & 1) * 4;
    int bk   = tid >> 5;
    int bc   = (tid & 31) * 4;

    for (int k0 = 0; k0 < D_DIM; k0 += 8) {
        int tok = stok[arow];
        float4 av = make_float4(0.f, 0.f, 0.f, 0.f);
        if (tok >= 0)
            av = *reinterpret_cast<const float4*>(x + (size_t)tok * D_DIM + k0 + akq);
        As[akq + 0][arow] = av.x;
        As[akq + 1][arow] = av.y;
        As[akq + 2][arow] = av.z;
        As[akq + 3][arow] = av.w;

        float4 bv = *reinterpret_cast<const float4*>(Wb + (size_t)(k0 + bk) * H_DIM + col0 + bc);
        *reinterpret_cast<float4*>(&Bs[bk][bc]) = bv;
        __syncthreads();

#pragma unroll
        for (int kk = 0; kk < 8; kk++) {
            float4 a0 = *reinterpret_cast<float4*>(&As[kk][ty * 8]);
            float4 a1 = *reinterpret_cast<float4*>(&As[kk][ty * 8 + 4]);
            float4 b0 = *reinterpret_cast<float4*>(&Bs[kk][tx * 8]);
            float4 b1v = *reinterpret_cast<float4*>(&Bs[kk][tx * 8 + 4]);
            float a[8] = {a0.x, a0.y, a0.z, a0.w, a1.x, a1.y, a1.z, a1.w};
            float b[8] = {b0.x, b0.y, b0.z, b0.w, b1v.x, b1v.y, b1v.z, b1v.w};
#pragma unroll
            for (int i = 0; i < 8; i++)
#pragma unroll
                for (int j = 0; j < 8; j++) acc[i][j] += a[i] * b[j];
        }
        __syncthreads();
    }

    const float* b1e = b1 + e * H_DIM;
    int colbase = col0 + tx * 8;
#pragma unroll
    for (int i = 0; i < 8; i++) {
        int r = row0 + ty * 8 + i;
        if (r < cnt) {
            float* hrow = g_h + ((size_t)e * T_TOK + r) * H_DIM + colbase;
#pragma unroll
            for (int j = 0; j < 8; j++)
                hrow[j] = gelu_exact(acc[i][j] + b1e[colbase + j]);
        }
    }
}

// ---------------------------------------------------------------------------
// GEMM2: g_h[n_e, H] @ W2[e][H, D]; epilogue: out[tok] += w * (y + b2[e])
// ---------------------------------------------------------------------------
__global__ __launch_bounds__(256) void gemm2_kernel(
    const float* __restrict__ W2,
    const float* __restrict__ b2,
    float* __restrict__ out)
{
    int e   = blockIdx.z;
    int cnt = g_cnt[e];
    int row0 = blockIdx.y * 128;
    if (row0 >= cnt) return;
    int col0 = blockIdx.x * 128;

    __shared__ float As[8][128];
    __shared__ float Bs[8][128];

    int tid = threadIdx.x;
    int tx = tid & 15, ty = tid >> 4;
    float acc[8][8];
#pragma unroll
    for (int i = 0; i < 8; i++)
#pragma unroll
        for (int j = 0; j < 8; j++) acc[i][j] = 0.f;

    const float* Wb = W2 + (size_t)e * H_DIM * D_DIM;
    const float* Ab = g_h + (size_t)e * T_TOK * H_DIM;

    int arow = tid >> 1;
    int akq  = (tid & 1) * 4;
    int bk   = tid >> 5;
    int bc   = (tid & 31) * 4;

    for (int k0 = 0; k0 < H_DIM; k0 += 8) {
        int r = row0 + arow;
        float4 av = make_float4(0.f, 0.f, 0.f, 0.f);
        if (r < cnt)
            av = *reinterpret_cast<const float4*>(Ab + (size_t)r * H_DIM + k0 + akq);
        As[akq + 0][arow] = av.x;
        As[akq + 1][arow] = av.y;
        As[akq + 2][arow] = av.z;
        As[akq + 3][arow] = av.w;

        float4 bv = *reinterpret_cast<const float4*>(Wb + (size_t)(k0 + bk) * D_DIM + col0 + bc);
        *reinterpret_cast<float4*>(&Bs[bk][bc]) = bv;
        __syncthreads();

#pragma unroll
        for (int kk = 0; kk < 8; kk++) {
            float4 a0 = *reinterpret_cast<float4*>(&As[kk][ty * 8]);
            float4 a1 = *reinterpret_cast<float4*>(&As[kk][ty * 8 + 4]);
            float4 b0 = *reinterpret_cast<float4*>(&Bs[kk][tx * 8]);
            float4 b1v = *reinterpret_cast<float4*>(&Bs[kk][tx * 8 + 4]);
            float a[8] = {a0.x, a0.y, a0.z, a0.w, a1.x, a1.y, a1.z, a1.w};
            float b[8] = {b0.x, b0.y, b0.z, b0.w, b1v.x, b1v.y, b1v.z, b1v.w};
#pragma unroll
            for (int i = 0; i < 8; i++)
#pragma unroll
                for (int j = 0; j < 8; j++) acc[i][j] += a[i] * b[j];
        }
        __syncthreads();
    }

    const float* b2e = b2 + e * D_DIM;
    int colbase = col0 + tx * 8;
#pragma unroll
    for (int i = 0; i < 8; i++) {
        int r = row0 + ty * 8 + i;
        if (r < cnt) {
            int   tok = g_btok[e * T_TOK + r];
            float w   = g_bw[e * T_TOK + r];
            float* orow = out + (size_t)tok * D_DIM + colbase;
#pragma unroll
            for (int j = 0; j < 8; j++)
                atomicAdd(&orow[j], w * (acc[i][j] + b2e[colbase + j]));
        }
    }
}

// ---------------------------------------------------------------------------
// aux loss
// ---------------------------------------------------------------------------
__global__ void finalize_kernel(float* __restrict__ out) {
    int tot = 0;
#pragma unroll
    for (int e = 0; e < NE; e++) tot += g_cnt[e];
    float denom = fmaxf((float)tot, 1.f);
    float s = 0.f;
#pragma unroll
    for (int e = 0; e < NE; e++)
        s += (g_imp[e] / (float)T_TOK) * ((float)g_cnt[e] / denom);
    out[(size_t)T_TOK * D_DIM] = (float)NE * s;
}

// ---------------------------------------------------------------------------
extern "C" void kernel_launch(void* const* d_in, const int* in_sizes, int n_in,
                              void* d_out, int out_size)
{
    const float* x  = (const float*)d_in[0];
    const float* Wr = (const float*)d_in[1];
    const float* br = (const float*)d_in[2];
    const float* W1 = (const float*)d_in[3];
    const float* b1 = (const float*)d_in[4];
    const float* W2 = (const float*)d_in[5];
    const float* b2 = (const float*)d_in[6];
    float* out = (float*)d_out;

    zero_kernel<<<4096, 512>>>(out);
    router_kernel<<<T_TOK / 8, 256>>>(x, Wr, br);
    gemm1_kernel<<<dim3(H_DIM / 128, T_TOK / 128, NE), 256>>>(x, W1, b1);
    gemm2_kernel<<<dim3(D_DIM / 128, T_TOK / 128, NE), 256>>>(W2, b2, out);
    if (out_size > T_TOK * D_DIM)
        finalize_kernel<<<1, 1>>>(out);
}

// round 3
// speedup vs baseline: 2.3155x; 2.3155x over previous
#include <cuda_runtime.h>
#include <cuda_bf16.h>
#include <math.h>

#define T_TOK 8192
#define D_DIM 1024
#define H_DIM 2048
#define NE    8
#define STAGES 3
#define CH    64

typedef unsigned int u32;
typedef unsigned long long u64;

// ---------------- static device scratch ----------------
__device__ int   g_cnt[NE];
__device__ float g_imp[NE];
__device__ int   g_btok[NE * T_TOK];
__device__ float g_bw[NE * T_TOK];
__device__ __nv_bfloat16 g_xh[(size_t)T_TOK * D_DIM];
__device__ __nv_bfloat16 g_xl[(size_t)T_TOK * D_DIM];
__device__ __nv_bfloat16 g_w1h[(size_t)NE * H_DIM * D_DIM];   // W1^T hi [e][h][d]
__device__ __nv_bfloat16 g_w1l[(size_t)NE * H_DIM * D_DIM];
__device__ __nv_bfloat16 g_w2h[(size_t)NE * D_DIM * H_DIM];   // W2^T hi [e][d][h]
__device__ __nv_bfloat16 g_w2l[(size_t)NE * D_DIM * H_DIM];
__device__ __nv_bfloat16 g_hh[(size_t)NE * T_TOK * H_DIM];    // hidden hi
__device__ __nv_bfloat16 g_hl[(size_t)NE * T_TOK * H_DIM];    // hidden lo

// ---------------- helpers ----------------
__device__ __forceinline__ u32 cvta_smem(const void* p) {
    u32 a;
    asm("{ .reg .u64 t; cvta.to.shared.u64 t, %1; cvt.u32.u64 %0, t; }" : "=r"(a) : "l"(p));
    return a;
}
__device__ __forceinline__ void cp16(u32 dst, const void* src) {
    asm volatile("cp.async.cg.shared.global [%0], [%1], 16;" :: "r"(dst), "l"(src));
}
__device__ __forceinline__ void cp_commit() { asm volatile("cp.async.commit_group;"); }
__device__ __forceinline__ void ldsm4(u32& r0, u32& r1, u32& r2, u32& r3, u32 addr) {
    asm volatile("ldmatrix.sync.aligned.m8n8.x4.shared.b16 {%0,%1,%2,%3}, [%4];"
                 : "=r"(r0), "=r"(r1), "=r"(r2), "=r"(r3) : "r"(addr));
}
__device__ __forceinline__ void mma16816(float* c, u32 a0, u32 a1, u32 a2, u32 a3,
                                         u32 b0, u32 b1) {
    asm volatile("mma.sync.aligned.m16n8k16.row.col.f32.bf16.bf16.f32 "
                 "{%0,%1,%2,%3}, {%4,%5,%6,%7}, {%8,%9}, {%0,%1,%2,%3};"
                 : "+f"(c[0]), "+f"(c[1]), "+f"(c[2]), "+f"(c[3])
                 : "r"(a0), "r"(a1), "r"(a2), "r"(a3), "r"(b0), "r"(b1));
}
__device__ __forceinline__ u32 swz(u32 o) { return o ^ ((o >> 3) & 0x70); }
__device__ __forceinline__ u32 pack_bf2(__nv_bfloat16 a, __nv_bfloat16 b) {
    unsigned short ua = *reinterpret_cast<unsigned short*>(&a);
    unsigned short ub = *reinterpret_cast<unsigned short*>(&b);
    return (u32)ua | ((u32)ub << 16);
}
__device__ __forceinline__ float gelu_exact(float v) {
    return 0.5f * v * (1.f + erff(v * 0.70710678118654752f));
}

#define SMEM_BYTES (1024 + STAGES * 32768)

// ---------------------------------------------------------------------------
__global__ void zero_kernel(float* __restrict__ out) {
    size_t n4 = (size_t)T_TOK * D_DIM / 4;
    size_t i  = (size_t)blockIdx.x * blockDim.x + threadIdx.x;
    float4 z = make_float4(0.f, 0.f, 0.f, 0.f);
    for (; i < n4; i += (size_t)gridDim.x * blockDim.x)
        reinterpret_cast<float4*>(out)[i] = z;
    if (blockIdx.x == 0 && threadIdx.x < NE) {
        g_cnt[threadIdx.x] = 0;
        g_imp[threadIdx.x] = 0.f;
    }
}

// x fp32 -> bf16 hi/lo planes
__global__ void xsplit_kernel(const float* __restrict__ x) {
    size_t i = (size_t)blockIdx.x * blockDim.x + threadIdx.x;   // one float4 each
    float4 v = reinterpret_cast<const float4*>(x)[i];
    __nv_bfloat16 h0 = __float2bfloat16(v.x), h1 = __float2bfloat16(v.y);
    __nv_bfloat16 h2 = __float2bfloat16(v.z), h3 = __float2bfloat16(v.w);
    __nv_bfloat16 l0 = __float2bfloat16(v.x - __bfloat162float(h0));
    __nv_bfloat16 l1 = __float2bfloat16(v.y - __bfloat162float(h1));
    __nv_bfloat16 l2 = __float2bfloat16(v.z - __bfloat162float(h2));
    __nv_bfloat16 l3 = __float2bfloat16(v.w - __bfloat162float(h3));
    reinterpret_cast<uint2*>(g_xh)[i] = make_uint2(pack_bf2(h0, h1), pack_bf2(h2, h3));
    reinterpret_cast<uint2*>(g_xl)[i] = make_uint2(pack_bf2(l0, l1), pack_bf2(l2, l3));
}

// weight transpose + split: in[e][R][C] fp32 -> out[e][C][R] bf16 planes
__global__ void convsplit_kernel(const float* __restrict__ in,
                                 __nv_bfloat16* __restrict__ ohi,
                                 __nv_bfloat16* __restrict__ olo,
                                 int R, int C)
{
    __shared__ float s[32][33];
    int e  = blockIdx.z;
    int c0 = blockIdx.x * 32, r0 = blockIdx.y * 32;
    const float* ip = in + (size_t)e * R * C;
#pragma unroll
    for (int k = 0; k < 32; k += 8)
        s[threadIdx.y + k][threadIdx.x] =
            ip[(size_t)(r0 + threadIdx.y + k) * C + c0 + threadIdx.x];
    __syncthreads();
#pragma unroll
    for (int k = 0; k < 32; k += 8) {
        float v = s[threadIdx.x][threadIdx.y + k];
        __nv_bfloat16 h = __float2bfloat16(v);
        __nv_bfloat16 l = __float2bfloat16(v - __bfloat162float(h));
        size_t o = ((size_t)e * C + c0 + threadIdx.y + k) * R + r0 + threadIdx.x;
        ohi[o] = h;
        olo[o] = l;
    }
}

// ---------------------------------------------------------------------------
__global__ __launch_bounds__(256) void router_kernel(
    const float* __restrict__ x,
    const float* __restrict__ Wr,
    const float* __restrict__ br)
{
    __shared__ float sWr[D_DIM * NE];
    __shared__ float s_imp[NE];
    int tid = threadIdx.x;
    for (int i = tid; i < D_DIM * NE; i += 256) sWr[i] = Wr[i];
    if (tid < NE) s_imp[tid] = 0.f;
    __syncthreads();

    int warp = tid >> 5, lane = tid & 31;
    int t = blockIdx.x * 8 + warp;

    float acc[NE];
#pragma unroll
    for (int e = 0; e < NE; e++) acc[e] = 0.f;

    const float* xr = x + (size_t)t * D_DIM;
    for (int d = lane; d < D_DIM; d += 32) {
        float xv = xr[d];
#pragma unroll
        for (int e = 0; e < NE; e++) acc[e] += xv * sWr[d * NE + e];
    }
#pragma unroll
    for (int e = 0; e < NE; e++) {
#pragma unroll
        for (int off = 16; off > 0; off >>= 1)
            acc[e] += __shfl_down_sync(0xffffffffu, acc[e], off);
    }

    if (lane == 0) {
        float p[NE];
        float mx = -1e30f;
#pragma unroll
        for (int e = 0; e < NE; e++) { p[e] = acc[e] + br[e]; mx = fmaxf(mx, p[e]); }
        float s = 0.f;
#pragma unroll
        for (int e = 0; e < NE; e++) { p[e] = expf(p[e] - mx); s += p[e]; }
        float inv = 1.f / s;
#pragma unroll
        for (int e = 0; e < NE; e++) {
            p[e] *= inv;
            atomicAdd(&s_imp[e], p[e]);
        }
        int i0 = 0;
#pragma unroll
        for (int e = 1; e < NE; e++) if (p[e] > p[i0]) i0 = e;
        int i1 = -1;
        float best1 = -1.f;
#pragma unroll
        for (int e = 0; e < NE; e++) {
            if (e == i0) continue;
            if (p[e] > best1) { best1 = p[e]; i1 = e; }
        }
        float w0 = p[i0], w1 = p[i1];
        float ws = fmaxf(w0 + w1, 1e-9f);
        w0 /= ws; w1 /= ws;

        int s0 = atomicAdd(&g_cnt[i0], 1);
        g_btok[i0 * T_TOK + s0] = t;
        g_bw[i0 * T_TOK + s0]   = w0;
        int s1 = atomicAdd(&g_cnt[i1], 1);
        g_btok[i1 * T_TOK + s1] = t;
        g_bw[i1 * T_TOK + s1]   = w1;
    }
    __syncthreads();
    if (tid < NE) atomicAdd(&g_imp[tid], s_imp[tid]);
}

// ---------------------------------------------------------------------------
// GEMM1: gathered x-planes @ W1-planes (expanded K'=3*1024) -> gelu -> g_hh/g_hl
// ---------------------------------------------------------------------------
__global__ __launch_bounds__(256) void gemm1_mma(const float* __restrict__ b1)
{
    int e    = blockIdx.z;
    int cnt  = g_cnt[e];
    int row0 = blockIdx.y * 128;
    if (row0 >= cnt) return;
    int n0 = blockIdx.x * 128;

    extern __shared__ char smem[];
    float* sBias = (float*)smem;
    int*   stok  = (int*)(smem + 512);
    u32 tb = cvta_smem(smem + 1024);

    int tid = threadIdx.x, lane = tid & 31, wid = tid >> 5;
    if (tid < 128) {
        sBias[tid] = b1[e * H_DIM + n0 + tid];
        int r = row0 + tid;
        stok[tid] = (r < cnt) ? g_btok[e * T_TOK + r] : 0;
    }
    __syncthreads();

    const int NCH = 3 * D_DIM / CH;   // 48
    auto issue = [&](int it, int s) {
        int k0e = it * CH;
        int seg = k0e >> 10;
        int kb  = k0e & (D_DIM - 1);
        const __nv_bfloat16* Ap = (seg == 1) ? g_xl : g_xh;
        const __nv_bfloat16* Bp = ((seg == 2) ? g_w1l : g_w1h) + ((size_t)e * H_DIM + n0) * D_DIM;
        u32 base = tb + s * 32768;
#pragma unroll
        for (int i = 0; i < 4; i++) {
            int idx = i * 256 + tid;
            int row = idx >> 3, c = idx & 7;
            cp16(base + swz(row * 128 + c * 16),
                 Ap + (size_t)stok[row] * D_DIM + kb + c * 8);
            cp16(base + 16384 + swz(row * 128 + c * 16),
                 Bp + (size_t)row * D_DIM + kb + c * 8);
        }
        cp_commit();
    };
    issue(0, 0);
    issue(1, 1);

    float acc[4][4][4];
#pragma unroll
    for (int i = 0; i < 4; i++)
#pragma unroll
        for (int j = 0; j < 4; j++)
#pragma unroll
            for (int k = 0; k < 4; k++) acc[i][j][k] = 0.f;

    int wm = wid & 1, wn = wid >> 1;

    for (int it = 0; it < NCH; ++it) {
        asm volatile("cp.async.wait_group 1;" ::: "memory");
        __syncthreads();
        if (it + 2 < NCH) issue(it + 2, (it + 2) % STAGES);
        u32 base = tb + (it % STAGES) * 32768;
#pragma unroll
        for (int ks = 0; ks < 4; ++ks) {
            u32 a[4][4], b[2][4];
            int kby = ks * 32 + (lane >> 4) * 16;
#pragma unroll
            for (int mf = 0; mf < 4; ++mf) {
                int rr = wm * 64 + mf * 16 + (lane & 15);
                ldsm4(a[mf][0], a[mf][1], a[mf][2], a[mf][3], base + swz(rr * 128 + kby));
            }
#pragma unroll
            for (int nf = 0; nf < 2; ++nf) {
                int rr = wn * 32 + nf * 16 + (lane & 15);
                ldsm4(b[nf][0], b[nf][1], b[nf][2], b[nf][3],
                      base + 16384 + swz(rr * 128 + kby));
            }
#pragma unroll
            for (int mf = 0; mf < 4; ++mf)
#pragma unroll
                for (int nf = 0; nf < 4; ++nf) {
                    int g = nf >> 1, h = nf & 1;
                    mma16816(acc[mf][nf], a[mf][0], a[mf][1], a[mf][2], a[mf][3],
                             b[g][h], b[g][2 + h]);
                }
        }
    }

    // epilogue: bias + gelu + split
#pragma unroll
    for (int mf = 0; mf < 4; ++mf) {
        int rb = row0 + wm * 64 + mf * 16 + (lane >> 2);
#pragma unroll
        for (int half = 0; half < 2; ++half) {
            int r = rb + half * 8;
            if (r < cnt) {
                size_t rowoff = ((size_t)e * T_TOK + r) * H_DIM;
#pragma unroll
                for (int nf = 0; nf < 4; ++nf) {
                    int cl = wn * 32 + nf * 8 + (lane & 3) * 2;
                    float v0 = gelu_exact(acc[mf][nf][half * 2 + 0] + sBias[cl]);
                    float v1 = gelu_exact(acc[mf][nf][half * 2 + 1] + sBias[cl + 1]);
                    __nv_bfloat16 h0 = __float2bfloat16(v0), h1 = __float2bfloat16(v1);
                    __nv_bfloat16 l0 = __float2bfloat16(v0 - __bfloat162float(h0));
                    __nv_bfloat16 l1 = __float2bfloat16(v1 - __bfloat162float(h1));
                    *reinterpret_cast<u32*>(g_hh + rowoff + n0 + cl) = pack_bf2(h0, h1);
                    *reinterpret_cast<u32*>(g_hl + rowoff + n0 + cl) = pack_bf2(l0, l1);
                }
            }
        }
    }
}

// ---------------------------------------------------------------------------
// GEMM2: hidden-planes @ W2-planes (expanded K'=3*2048); weighted atomic combine
// ---------------------------------------------------------------------------
__global__ __launch_bounds__(256) void gemm2_mma(const float* __restrict__ b2,
                                                 float* __restrict__ out)
{
    int e    = blockIdx.z;
    int cnt  = g_cnt[e];
    int row0 = blockIdx.y * 128;
    if (row0 >= cnt) return;
    int n0 = blockIdx.x * 128;

    extern __shared__ char smem[];
    float* sBias = (float*)smem;
    u32 tb = cvta_smem(smem + 1024);

    int tid = threadIdx.x, lane = tid & 31, wid = tid >> 5;
    if (tid < 128) sBias[tid] = b2[e * D_DIM + n0 + tid];
    __syncthreads();

    const int NCH = 3 * H_DIM / CH;   // 96
    auto issue = [&](int it, int s) {
        int k0e = it * CH;
        int seg = k0e >> 11;
        int kb  = k0e & (H_DIM - 1);
        const __nv_bfloat16* Ap = ((seg == 1) ? g_hl : g_hh) + (size_t)e * T_TOK * H_DIM;
        const __nv_bfloat16* Bp = ((seg == 2) ? g_w2l : g_w2h) + ((size_t)e * D_DIM + n0) * H_DIM;
        u32 base = tb + s * 32768;
#pragma unroll
        for (int i = 0; i < 4; i++) {
            int idx = i * 256 + tid;
            int row = idx >> 3, c = idx & 7;
            int rr = row0 + row;
            if (rr >= cnt) rr = cnt - 1;
            cp16(base + swz(row * 128 + c * 16),
                 Ap + (size_t)rr * H_DIM + kb + c * 8);
            cp16(base + 16384 + swz(row * 128 + c * 16),
                 Bp + (size_t)row * H_DIM + kb + c * 8);
        }
        cp_commit();
    };
    issue(0, 0);
    issue(1, 1);

    float acc[4][4][4];
#pragma unroll
    for (int i = 0; i < 4; i++)
#pragma unroll
        for (int j = 0; j < 4; j++)
#pragma unroll
            for (int k = 0; k < 4; k++) acc[i][j][k] = 0.f;

    int wm = wid & 1, wn = wid >> 1;

    for (int it = 0; it < NCH; ++it) {
        asm volatile("cp.async.wait_group 1;" ::: "memory");
        __syncthreads();
        if (it + 2 < NCH) issue(it + 2, (it + 2) % STAGES);
        u32 base = tb + (it % STAGES) * 32768;
#pragma unroll
        for (int ks = 0; ks < 4; ++ks) {
            u32 a[4][4], b[2][4];
            int kby = ks * 32 + (lane >> 4) * 16;
#pragma unroll
            for (int mf = 0; mf < 4; ++mf) {
                int rr = wm * 64 + mf * 16 + (lane & 15);
                ldsm4(a[mf][0], a[mf][1], a[mf][2], a[mf][3], base + swz(rr * 128 + kby));
            }
#pragma unroll
            for (int nf = 0; nf < 2; ++nf) {
                int rr = wn * 32 + nf * 16 + (lane & 15);
                ldsm4(b[nf][0], b[nf][1], b[nf][2], b[nf][3],
                      base + 16384 + swz(rr * 128 + kby));
            }
#pragma unroll
            for (int mf = 0; mf < 4; ++mf)
#pragma unroll
                for (int nf = 0; nf < 4; ++nf) {
                    int g = nf >> 1, h = nf & 1;
                    mma16816(acc[mf][nf], a[mf][0], a[mf][1], a[mf][2], a[mf][3],
                             b[g][h], b[g][2 + h]);
                }
        }
    }

    // epilogue: out[tok] += w * (y + b2)
#pragma unroll
    for (int mf = 0; mf < 4; ++mf) {
        int rb = row0 + wm * 64 + mf * 16 + (lane >> 2);
#pragma unroll
        for (int half = 0; half < 2; ++half) {
            int r = rb + half * 8;
            if (r < cnt) {
                int   tok = g_btok[e * T_TOK + r];
                float w   = g_bw[e * T_TOK + r];
                float* orow = out + (size_t)tok * D_DIM + n0;
#pragma unroll
                for (int nf = 0; nf < 4; ++nf) {
                    int cl = wn * 32 + nf * 8 + (lane & 3) * 2;
                    atomicAdd(orow + cl,     w * (acc[mf][nf][half * 2 + 0] + sBias[cl]));
                    atomicAdd(orow + cl + 1, w * (acc[mf][nf][half * 2 + 1] + sBias[cl + 1]));
                }
            }
        }
    }
}

// ---------------------------------------------------------------------------
__global__ void finalize_kernel(float* __restrict__ out) {
    int tot = 0;
#pragma unroll
    for (int e = 0; e < NE; e++) tot += g_cnt[e];
    float denom = fmaxf((float)tot, 1.f);
    float s = 0.f;
#pragma unroll
    for (int e = 0; e < NE; e++)
        s += (g_imp[e] / (float)T_TOK) * ((float)g_cnt[e] / denom);
    out[(size_t)T_TOK * D_DIM] = (float)NE * s;
}

// ---------------------------------------------------------------------------
extern "C" void kernel_launch(void* const* d_in, const int* in_sizes, int n_in,
                              void* d_out, int out_size)
{
    const float* x  = (const float*)d_in[0];
    const float* Wr = (const float*)d_in[1];
    const float* br = (const float*)d_in[2];
    const float* W1 = (const float*)d_in[3];
    const float* b1 = (const float*)d_in[4];
    const float* W2 = (const float*)d_in[5];
    const float* b2 = (const float*)d_in[6];
    float* out = (float*)d_out;

    cudaFuncSetAttribute(gemm1_mma, cudaFuncAttributeMaxDynamicSharedMemorySize, SMEM_BYTES);
    cudaFuncSetAttribute(gemm2_mma, cudaFuncAttributeMaxDynamicSharedMemorySize, SMEM_BYTES);

    __nv_bfloat16 *w1h, *w1l, *w2h, *w2l;
    cudaGetSymbolAddress((void**)&w1h, g_w1h);
    cudaGetSymbolAddress((void**)&w1l, g_w1l);
    cudaGetSymbolAddress((void**)&w2h, g_w2h);
    cudaGetSymbolAddress((void**)&w2l, g_w2l);

    zero_kernel<<<2048, 512>>>(out);
    xsplit_kernel<<<(T_TOK * D_DIM / 4) / 512, 512>>>(x);
    convsplit_kernel<<<dim3(H_DIM / 32, D_DIM / 32, NE), dim3(32, 8)>>>(W1, w1h, w1l, D_DIM, H_DIM);
    convsplit_kernel<<<dim3(D_DIM / 32, H_DIM / 32, NE), dim3(32, 8)>>>(W2, w2h, w2l, H_DIM, D_DIM);
    router_kernel<<<T_TOK / 8, 256>>>(x, Wr, br);
    gemm1_mma<<<dim3(H_DIM / 128, T_TOK / 128, NE), 256, SMEM_BYTES>>>(b1);
    gemm2_mma<<<dim3(D_DIM / 128, T_TOK / 128, NE), 256, SMEM_BYTES>>>(b2, out);
    if (out_size > T_TOK * D_DIM)
        finalize_kernel<<<1, 1>>>(out);
}

// round 4
// speedup vs baseline: 2.4257x; 1.0476x over previous
#include <cuda_runtime.h>
#include <cuda_fp16.h>
#include <math.h>

#define T_TOK 8192
#define D_DIM 1024
#define H_DIM 2048
#define NE    8
#define CH    32
#define STAGES 5
#define STG_BYTES 32768
#define SMEM_BYTES (1024 + STAGES * STG_BYTES)

typedef unsigned int u32;
typedef unsigned long long u64;

// ---------------- static device scratch ----------------
__device__ int   g_cnt[NE];
__device__ float g_imp[NE];
__device__ int   g_btok[NE * T_TOK];
__device__ float g_bw[NE * T_TOK];
__device__ __half g_xh[(size_t)T_TOK * D_DIM];
__device__ __half g_xl[(size_t)T_TOK * D_DIM];
__device__ __half g_w1h[(size_t)NE * H_DIM * D_DIM];   // W1^T hi [e][h][d]
__device__ __half g_w1l[(size_t)NE * H_DIM * D_DIM];
__device__ __half g_w2h[(size_t)NE * D_DIM * H_DIM];   // W2^T hi [e][d][h]
__device__ __half g_w2l[(size_t)NE * D_DIM * H_DIM];
__device__ __half g_hh[(size_t)NE * T_TOK * H_DIM];    // hidden hi
__device__ __half g_hl[(size_t)NE * T_TOK * H_DIM];    // hidden lo

// ---------------- helpers ----------------
__device__ __forceinline__ u32 cvta_smem(const void* p) {
    u32 a;
    asm("{ .reg .u64 t; cvta.to.shared.u64 t, %1; cvt.u32.u64 %0, t; }" : "=r"(a) : "l"(p));
    return a;
}
__device__ __forceinline__ void cp16(u32 dst, const void* src) {
    asm volatile("cp.async.cg.shared.global [%0], [%1], 16;" :: "r"(dst), "l"(src));
}
__device__ __forceinline__ void cp_commit() { asm volatile("cp.async.commit_group;"); }
__device__ __forceinline__ void ldsm4(u32& r0, u32& r1, u32& r2, u32& r3, u32 addr) {
    asm volatile("ldmatrix.sync.aligned.m8n8.x4.shared.b16 {%0,%1,%2,%3}, [%4];"
                 : "=r"(r0), "=r"(r1), "=r"(r2), "=r"(r3) : "r"(addr));
}
__device__ __forceinline__ void mma_f32(float* c, const u32* a, u32 b0, u32 b1) {
    asm volatile("mma.sync.aligned.m16n8k16.row.col.f32.f16.f16.f32 "
                 "{%0,%1,%2,%3}, {%4,%5,%6,%7}, {%8,%9}, {%0,%1,%2,%3};"
                 : "+f"(c[0]), "+f"(c[1]), "+f"(c[2]), "+f"(c[3])
                 : "r"(a[0]), "r"(a[1]), "r"(a[2]), "r"(a[3]), "r"(b0), "r"(b1));
}
__device__ __forceinline__ void mma_f16(u32* c, const u32* a, u32 b0, u32 b1) {
    asm volatile("mma.sync.aligned.m16n8k16.row.col.f16.f16.f16.f16 "
                 "{%0,%1}, {%2,%3,%4,%5}, {%6,%7}, {%0,%1};"
                 : "+r"(c[0]), "+r"(c[1])
                 : "r"(a[0]), "r"(a[1]), "r"(a[2]), "r"(a[3]), "r"(b0), "r"(b1));
}
// 64B-row swizzle (SW64): XOR byte bits[5:4] with row bits[2:1]
__device__ __forceinline__ u32 swz64(u32 o) { return o ^ ((o >> 3) & 0x30); }
__device__ __forceinline__ u32 pack_h2(__half a, __half b) {
    unsigned short ua = *reinterpret_cast<unsigned short*>(&a);
    unsigned short ub = *reinterpret_cast<unsigned short*>(&b);
    return (u32)ua | ((u32)ub << 16);
}
__device__ __forceinline__ float gelu_exact(float v) {
    return 0.5f * v * (1.f + erff(v * 0.70710678118654752f));
}

// ---------------------------------------------------------------------------
__global__ void zero_kernel(float* __restrict__ out) {
    size_t n4 = (size_t)T_TOK * D_DIM / 4;
    size_t i  = (size_t)blockIdx.x * blockDim.x + threadIdx.x;
    float4 z = make_float4(0.f, 0.f, 0.f, 0.f);
    for (; i < n4; i += (size_t)gridDim.x * blockDim.x)
        reinterpret_cast<float4*>(out)[i] = z;
    if (blockIdx.x == 0 && threadIdx.x < NE) {
        g_cnt[threadIdx.x] = 0;
        g_imp[threadIdx.x] = 0.f;
    }
}

// x fp32 -> fp16 hi/lo planes
__global__ void xsplit_kernel(const float* __restrict__ x) {
    size_t i = (size_t)blockIdx.x * blockDim.x + threadIdx.x;
    float4 v = reinterpret_cast<const float4*>(x)[i];
    __half h0 = __float2half_rn(v.x), h1 = __float2half_rn(v.y);
    __half h2 = __float2half_rn(v.z), h3 = __float2half_rn(v.w);
    __half l0 = __float2half_rn(v.x - __half2float(h0));
    __half l1 = __float2half_rn(v.y - __half2float(h1));
    __half l2 = __float2half_rn(v.z - __half2float(h2));
    __half l3 = __float2half_rn(v.w - __half2float(h3));
    reinterpret_cast<uint2*>(g_xh)[i] = make_uint2(pack_h2(h0, h1), pack_h2(h2, h3));
    reinterpret_cast<uint2*>(g_xl)[i] = make_uint2(pack_h2(l0, l1), pack_h2(l2, l3));
}

// weight transpose + fp16 split: in[e][R][C] fp32 -> out[e][C][R]
__global__ void convsplit_kernel(const float* __restrict__ in,
                                 __half* __restrict__ ohi,
                                 __half* __restrict__ olo,
                                 int R, int C)
{
    __shared__ float s[32][33];
    int e  = blockIdx.z;
    int c0 = blockIdx.x * 32, r0 = blockIdx.y * 32;
    const float* ip = in + (size_t)e * R * C;
#pragma unroll
    for (int k = 0; k < 32; k += 8)
        s[threadIdx.y + k][threadIdx.x] =
            ip[(size_t)(r0 + threadIdx.y + k) * C + c0 + threadIdx.x];
    __syncthreads();
#pragma unroll
    for (int k = 0; k < 32; k += 8) {
        float v = s[threadIdx.x][threadIdx.y + k];
        __half h = __float2half_rn(v);
        __half l = __float2half_rn(v - __half2float(h));
        size_t o = ((size_t)e * C + c0 + threadIdx.y + k) * R + r0 + threadIdx.x;
        ohi[o] = h;
        olo[o] = l;
    }
}

// ---------------------------------------------------------------------------
__global__ __launch_bounds__(256) void router_kernel(
    const float* __restrict__ x,
    const float* __restrict__ Wr,
    const float* __restrict__ br)
{
    __shared__ float sWr[D_DIM * NE];
    __shared__ float s_imp[NE];
    int tid = threadIdx.x;
    for (int i = tid; i < D_DIM * NE; i += 256) sWr[i] = Wr[i];
    if (tid < NE) s_imp[tid] = 0.f;
    __syncthreads();

    int warp = tid >> 5, lane = tid & 31;
    int t = blockIdx.x * 8 + warp;

    float acc[NE];
#pragma unroll
    for (int e = 0; e < NE; e++) acc[e] = 0.f;

    const float* xr = x + (size_t)t * D_DIM;
    for (int d = lane; d < D_DIM; d += 32) {
        float xv = xr[d];
#pragma unroll
        for (int e = 0; e < NE; e++) acc[e] += xv * sWr[d * NE + e];
    }
#pragma unroll
    for (int e = 0; e < NE; e++) {
#pragma unroll
        for (int off = 16; off > 0; off >>= 1)
            acc[e] += __shfl_down_sync(0xffffffffu, acc[e], off);
    }

    if (lane == 0) {
        float p[NE];
        float mx = -1e30f;
#pragma unroll
        for (int e = 0; e < NE; e++) { p[e] = acc[e] + br[e]; mx = fmaxf(mx, p[e]); }
        float s = 0.f;
#pragma unroll
        for (int e = 0; e < NE; e++) { p[e] = expf(p[e] - mx); s += p[e]; }
        float inv = 1.f / s;
#pragma unroll
        for (int e = 0; e < NE; e++) {
            p[e] *= inv;
            atomicAdd(&s_imp[e], p[e]);
        }
        int i0 = 0;
#pragma unroll
        for (int e = 1; e < NE; e++) if (p[e] > p[i0]) i0 = e;
        int i1 = -1;
        float best1 = -1.f;
#pragma unroll
        for (int e = 0; e < NE; e++) {
            if (e == i0) continue;
            if (p[e] > best1) { best1 = p[e]; i1 = e; }
        }
        float w0 = p[i0], w1 = p[i1];
        float ws = fmaxf(w0 + w1, 1e-9f);
        w0 /= ws; w1 /= ws;

        int s0 = atomicAdd(&g_cnt[i0], 1);
        g_btok[i0 * T_TOK + s0] = t;
        g_bw[i0 * T_TOK + s0]   = w0;
        int s1 = atomicAdd(&g_cnt[i1], 1);
        g_btok[i1 * T_TOK + s1] = t;
        g_bw[i1 * T_TOK + s1]   = w1;
    }
    __syncthreads();
    if (tid < NE) atomicAdd(&g_imp[tid], s_imp[tid]);
}

// ---------------------------------------------------------------------------
// GEMM1: gathered x (hi/lo fp16) @ W1 planes; f32acc for hi*hi, f16acc for cross
// ---------------------------------------------------------------------------
__global__ __launch_bounds__(256) void gemm1_mma(const float* __restrict__ b1)
{
    int e    = blockIdx.z;
    int cnt  = g_cnt[e];
    int row0 = blockIdx.y * 128;
    if (row0 >= cnt) return;
    int n0 = blockIdx.x * 128;

    extern __shared__ char smem[];
    float* sBias = (float*)smem;
    int*   stok  = (int*)(smem + 512);
    u32 tb = cvta_smem(smem + 1024);

    int tid = threadIdx.x, lane = tid & 31, wid = tid >> 5;
    if (tid < 128) {
        sBias[tid] = b1[e * H_DIM + n0 + tid];
        int r = row0 + tid;
        stok[tid] = (r < cnt) ? g_btok[e * T_TOK + r] : 0;
    }
    __syncthreads();

    const __half* Bh = g_w1h + ((size_t)e * H_DIM + n0) * D_DIM;
    const __half* Bl = g_w1l + ((size_t)e * H_DIM + n0) * D_DIM;

    const int NCH = D_DIM / CH;   // 32
    auto issue = [&](int it, int s) {
        int k0 = it * CH;
        u32 base = tb + s * STG_BYTES;
#pragma unroll
        for (int t = 0; t < 2; t++) {
            int idx = t * 256 + tid;
            int row = idx >> 2, c = idx & 3;
            u32 so = swz64((row << 6) + (c << 4));
            size_t aoff = (size_t)stok[row] * D_DIM + k0 + c * 8;
            cp16(base + so,         g_xh + aoff);
            cp16(base + 8192 + so,  g_xl + aoff);
            size_t boff = (size_t)row * D_DIM + k0 + c * 8;
            cp16(base + 16384 + so, Bh + boff);
            cp16(base + 24576 + so, Bl + boff);
        }
        cp_commit();
    };
    issue(0, 0); issue(1, 1); issue(2, 2);

    float accF[4][4][4];
    u32   accH[4][4][2];
#pragma unroll
    for (int i = 0; i < 4; i++)
#pragma unroll
        for (int j = 0; j < 4; j++) {
#pragma unroll
            for (int k = 0; k < 4; k++) accF[i][j][k] = 0.f;
            accH[i][j][0] = 0u; accH[i][j][1] = 0u;
        }

    int wm = wid & 1, wn = wid >> 1;

    for (int it = 0; it < NCH; ++it) {
        asm volatile("cp.async.wait_group 2;" ::: "memory");
        __syncthreads();
        if (it + 3 < NCH) issue(it + 3, (it + 3) % STAGES);
        u32 base = tb + (it % STAGES) * STG_BYTES;
#pragma unroll
        for (int ks = 0; ks < 2; ++ks) {
            u32 ah[4][4], al[4][4], bh[2][4], bl[2][4];
            int kby = ks * 32 + (lane >> 4) * 16;
#pragma unroll
            for (int mf = 0; mf < 4; ++mf) {
                int rr = wm * 64 + mf * 16 + (lane & 15);
                u32 off = swz64((rr << 6) + kby);
                ldsm4(ah[mf][0], ah[mf][1], ah[mf][2], ah[mf][3], base + off);
                ldsm4(al[mf][0], al[mf][1], al[mf][2], al[mf][3], base + 8192 + off);
            }
#pragma unroll
            for (int g = 0; g < 2; ++g) {
                int rr = wn * 32 + g * 16 + (lane & 15);
                u32 off = swz64((rr << 6) + kby);
                ldsm4(bh[g][0], bh[g][1], bh[g][2], bh[g][3], base + 16384 + off);
                ldsm4(bl[g][0], bl[g][1], bl[g][2], bl[g][3], base + 24576 + off);
            }
#pragma unroll
            for (int mf = 0; mf < 4; ++mf)
#pragma unroll
                for (int nf = 0; nf < 4; ++nf) {
                    int g = nf >> 1, h = nf & 1;
                    mma_f32(accF[mf][nf], ah[mf], bh[g][h], bh[g][2 + h]);
                }
#pragma unroll
            for (int mf = 0; mf < 4; ++mf)
#pragma unroll
                for (int nf = 0; nf < 4; ++nf) {
                    int g = nf >> 1, h = nf & 1;
                    mma_f16(accH[mf][nf], ah[mf], bl[g][h], bl[g][2 + h]);
                }
#pragma unroll
            for (int mf = 0; mf < 4; ++mf)
#pragma unroll
                for (int nf = 0; nf < 4; ++nf) {
                    int g = nf >> 1, h = nf & 1;
                    mma_f16(accH[mf][nf], al[mf], bh[g][h], bh[g][2 + h]);
                }
        }
    }

    // epilogue: combine + bias + gelu + fp16 split
#pragma unroll
    for (int mf = 0; mf < 4; ++mf) {
        int rb = row0 + wm * 64 + mf * 16 + (lane >> 2);
#pragma unroll
        for (int half = 0; half < 2; ++half) {
            int r = rb + half * 8;
            if (r < cnt) {
                size_t rowoff = ((size_t)e * T_TOK + r) * H_DIM;
#pragma unroll
                for (int nf = 0; nf < 4; ++nf) {
                    int cl = wn * 32 + nf * 8 + (lane & 3) * 2;
                    __half2 cx = *reinterpret_cast<__half2*>(&accH[mf][nf][half]);
                    float v0 = gelu_exact(accF[mf][nf][half * 2 + 0] + __low2float(cx)  + sBias[cl]);
                    float v1 = gelu_exact(accF[mf][nf][half * 2 + 1] + __high2float(cx) + sBias[cl + 1]);
                    __half h0 = __float2half_rn(v0), h1 = __float2half_rn(v1);
                    __half l0 = __float2half_rn(v0 - __half2float(h0));
                    __half l1 = __float2half_rn(v1 - __half2float(h1));
                    *reinterpret_cast<u32*>(g_hh + rowoff + n0 + cl) = pack_h2(h0, h1);
                    *reinterpret_cast<u32*>(g_hl + rowoff + n0 + cl) = pack_h2(l0, l1);
                }
            }
        }
    }
}

// ---------------------------------------------------------------------------
// GEMM2: hidden (hi/lo) @ W2 planes; weighted atomic combine
// ---------------------------------------------------------------------------
__global__ __launch_bounds__(256) void gemm2_mma(const float* __restrict__ b2,
                                                 float* __restrict__ out)
{
    int e    = blockIdx.z;
    int cnt  = g_cnt[e];
    int row0 = blockIdx.y * 128;
    if (row0 >= cnt) return;
    int n0 = blockIdx.x * 128;

    extern __shared__ char smem[];
    float* sBias = (float*)smem;
    u32 tb = cvta_smem(smem + 1024);

    int tid = threadIdx.x, lane = tid & 31, wid = tid >> 5;
    if (tid < 128) sBias[tid] = b2[e * D_DIM + n0 + tid];
    __syncthreads();

    const __half* Ah = g_hh + (size_t)e * T_TOK * H_DIM;
    const __half* Al = g_hl + (size_t)e * T_TOK * H_DIM;
    const __half* Bh = g_w2h + ((size_t)e * D_DIM + n0) * H_DIM;
    const __half* Bl = g_w2l + ((size_t)e * D_DIM + n0) * H_DIM;

    const int NCH = H_DIM / CH;   // 64
    auto issue = [&](int it, int s) {
        int k0 = it * CH;
        u32 base = tb + s * STG_BYTES;
#pragma unroll
        for (int t = 0; t < 2; t++) {
            int idx = t * 256 + tid;
            int row = idx >> 2, c = idx & 3;
            int rr = row0 + row;
            if (rr >= cnt) rr = cnt - 1;
            u32 so = swz64((row << 6) + (c << 4));
            size_t aoff = (size_t)rr * H_DIM + k0 + c * 8;
            cp16(base + so,         Ah + aoff);
            cp16(base + 8192 + so,  Al + aoff);
            size_t boff = (size_t)row * H_DIM + k0 + c * 8;
            cp16(base + 16384 + so, Bh + boff);
            cp16(base + 24576 + so, Bl + boff);
        }
        cp_commit();
    };
    issue(0, 0); issue(1, 1); issue(2, 2);

    float accF[4][4][4];
    u32   accH[4][4][2];
#pragma unroll
    for (int i = 0; i < 4; i++)
#pragma unroll
        for (int j = 0; j < 4; j++) {
#pragma unroll
            for (int k = 0; k < 4; k++) accF[i][j][k] = 0.f;
            accH[i][j][0] = 0u; accH[i][j][1] = 0u;
        }

    int wm = wid & 1, wn = wid >> 1;

    for (int it = 0; it < NCH; ++it) {
        asm volatile("cp.async.wait_group 2;" ::: "memory");
        __syncthreads();
        if (it + 3 < NCH) issue(it + 3, (it + 3) % STAGES);
        u32 base = tb + (it % STAGES) * STG_BYTES;
#pragma unroll
        for (int ks = 0; ks < 2; ++ks) {
            u32 ah[4][4], al[4][4], bh[2][4], bl[2][4];
            int kby = ks * 32 + (lane >> 4) * 16;
#pragma unroll
            for (int mf = 0; mf < 4; ++mf) {
                int rr = wm * 64 + mf * 16 + (lane & 15);
                u32 off = swz64((rr << 6) + kby);
                ldsm4(ah[mf][0], ah[mf][1], ah[mf][2], ah[mf][3], base + off);
                ldsm4(al[mf][0], al[mf][1], al[mf][2], al[mf][3], base + 8192 + off);
            }
#pragma unroll
            for (int g = 0; g < 2; ++g) {
                int rr = wn * 32 + g * 16 + (lane & 15);
                u32 off = swz64((rr << 6) + kby);
                ldsm4(bh[g][0], bh[g][1], bh[g][2], bh[g][3], base + 16384 + off);
                ldsm4(bl[g][0], bl[g][1], bl[g][2], bl[g][3], base + 24576 + off);
            }
#pragma unroll
            for (int mf = 0; mf < 4; ++mf)
#pragma unroll
                for (int nf = 0; nf < 4; ++nf) {
                    int g = nf >> 1, h = nf & 1;
                    mma_f32(accF[mf][nf], ah[mf], bh[g][h], bh[g][2 + h]);
                }
#pragma unroll
            for (int mf = 0; mf < 4; ++mf)
#pragma unroll
                for (int nf = 0; nf < 4; ++nf) {
                    int g = nf >> 1, h = nf & 1;
                    mma_f16(accH[mf][nf], ah[mf], bl[g][h], bl[g][2 + h]);
                }
#pragma unroll
            for (int mf = 0; mf < 4; ++mf)
#pragma unroll
                for (int nf = 0; nf < 4; ++nf) {
                    int g = nf >> 1, h = nf & 1;
                    mma_f16(accH[mf][nf], al[mf], bh[g][h], bh[g][2 + h]);
                }
        }
    }

    // epilogue: out[tok] += w * (y + b2)
#pragma unroll
    for (int mf = 0; mf < 4; ++mf) {
        int rb = row0 + wm * 64 + mf * 16 + (lane >> 2);
#pragma unroll
        for (int half = 0; half < 2; ++half) {
            int r = rb + half * 8;
            if (r < cnt) {
                int   tok = g_btok[e * T_TOK + r];
                float w   = g_bw[e * T_TOK + r];
                float* orow = out + (size_t)tok * D_DIM + n0;
#pragma unroll
                for (int nf = 0; nf < 4; ++nf) {
                    int cl = wn * 32 + nf * 8 + (lane & 3) * 2;
                    __half2 cx = *reinterpret_cast<__half2*>(&accH[mf][nf][half]);
                    atomicAdd(orow + cl,
                              w * (accF[mf][nf][half * 2 + 0] + __low2float(cx)  + sBias[cl]));
                    atomicAdd(orow + cl + 1,
                              w * (accF[mf][nf][half * 2 + 1] + __high2float(cx) + sBias[cl + 1]));
                }
            }
        }
    }
}

// ---------------------------------------------------------------------------
__global__ void finalize_kernel(float* __restrict__ out) {
    int tot = 0;
#pragma unroll
    for (int e = 0; e < NE; e++) tot += g_cnt[e];
    float denom = fmaxf((float)tot, 1.f);
    float s = 0.f;
#pragma unroll
    for (int e = 0; e < NE; e++)
        s += (g_imp[e] / (float)T_TOK) * ((float)g_cnt[e] / denom);
    out[(size_t)T_TOK * D_DIM] = (float)NE * s;
}

// ---------------------------------------------------------------------------
extern "C" void kernel_launch(void* const* d_in, const int* in_sizes, int n_in,
                              void* d_out, int out_size)
{
    const float* x  = (const float*)d_in[0];
    const float* Wr = (const float*)d_in[1];
    const float* br = (const float*)d_in[2];
    const float* W1 = (const float*)d_in[3];
    const float* b1 = (const float*)d_in[4];
    const float* W2 = (const float*)d_in[5];
    const float* b2 = (const float*)d_in[6];
    float* out = (float*)d_out;

    cudaFuncSetAttribute(gemm1_mma, cudaFuncAttributeMaxDynamicSharedMemorySize, SMEM_BYTES);
    cudaFuncSetAttribute(gemm2_mma, cudaFuncAttributeMaxDynamicSharedMemorySize, SMEM_BYTES);

    __half *w1h, *w1l, *w2h, *w2l;
    cudaGetSymbolAddress((void**)&w1h, g_w1h);
    cudaGetSymbolAddress((void**)&w1l, g_w1l);
    cudaGetSymbolAddress((void**)&w2h, g_w2h);
    cudaGetSymbolAddress((void**)&w2l, g_w2l);

    zero_kernel<<<2048, 512>>>(out);
    xsplit_kernel<<<(T_TOK * D_DIM / 4) / 512, 512>>>(x);
    convsplit_kernel<<<dim3(H_DIM / 32, D_DIM / 32, NE), dim3(32, 8)>>>(W1, w1h, w1l, D_DIM, H_DIM);
    convsplit_kernel<<<dim3(D_DIM / 32, H_DIM / 32, NE), dim3(32, 8)>>>(W2, w2h, w2l, H_DIM, D_DIM);
    router_kernel<<<T_TOK / 8, 256>>>(x, Wr, br);
    gemm1_mma<<<dim3(H_DIM / 128, T_TOK / 128, NE), 256, SMEM_BYTES>>>(b1);
    gemm2_mma<<<dim3(D_DIM / 128, T_TOK / 128, NE), 256, SMEM_BYTES>>>(b2, out);
    if (out_size > T_TOK * D_DIM)
        finalize_kernel<<<1, 1>>>(out);
}

// round 5
// speedup vs baseline: 3.1958x; 1.3175x over previous
#include <cuda_runtime.h>
#include <cuda_fp16.h>
#include <math.h>

#define T_TOK 8192
#define D_DIM 1024
#define H_DIM 2048
#define NE    8
#define CH    32
#define STAGES 5
#define STG_BYTES 24576
#define SMEM_BYTES (1024 + STAGES * STG_BYTES)

typedef unsigned int u32;
typedef unsigned long long u64;

// ---------------- static device scratch ----------------
__device__ int   g_cnt[NE];
__device__ float g_imp[NE];
__device__ int   g_btok[NE * T_TOK];
__device__ float g_bw[NE * T_TOK];
__device__ __half g_xh[(size_t)T_TOK * D_DIM];
__device__ __half g_xl[(size_t)T_TOK * D_DIM];
__device__ __half g_w1[(size_t)NE * H_DIM * D_DIM];    // W1^T fp16 [e][h][d]
__device__ __half g_w2[(size_t)NE * D_DIM * H_DIM];    // W2^T fp16 [e][d][h]
__device__ __half g_hh[(size_t)NE * T_TOK * H_DIM];    // hidden hi
__device__ __half g_hl[(size_t)NE * T_TOK * H_DIM];    // hidden lo

// ---------------- helpers ----------------
__device__ __forceinline__ u32 cvta_smem(const void* p) {
    u32 a;
    asm("{ .reg .u64 t; cvta.to.shared.u64 t, %1; cvt.u32.u64 %0, t; }" : "=r"(a) : "l"(p));
    return a;
}
__device__ __forceinline__ void cp16(u32 dst, const void* src) {
    asm volatile("cp.async.cg.shared.global [%0], [%1], 16;" :: "r"(dst), "l"(src));
}
__device__ __forceinline__ void cp_commit() { asm volatile("cp.async.commit_group;"); }
__device__ __forceinline__ void ldsm4(u32& r0, u32& r1, u32& r2, u32& r3, u32 addr) {
    asm volatile("ldmatrix.sync.aligned.m8n8.x4.shared.b16 {%0,%1,%2,%3}, [%4];"
                 : "=r"(r0), "=r"(r1), "=r"(r2), "=r"(r3) : "r"(addr));
}
__device__ __forceinline__ void mma_f32(float* c, const u32* a, u32 b0, u32 b1) {
    asm volatile("mma.sync.aligned.m16n8k16.row.col.f32.f16.f16.f32 "
                 "{%0,%1,%2,%3}, {%4,%5,%6,%7}, {%8,%9}, {%0,%1,%2,%3};"
                 : "+f"(c[0]), "+f"(c[1]), "+f"(c[2]), "+f"(c[3])
                 : "r"(a[0]), "r"(a[1]), "r"(a[2]), "r"(a[3]), "r"(b0), "r"(b1));
}
// 64B-row swizzle
__device__ __forceinline__ u32 swz64(u32 o) { return o ^ ((o >> 3) & 0x30); }
__device__ __forceinline__ u32 pack_h2(__half a, __half b) {
    unsigned short ua = *reinterpret_cast<unsigned short*>(&a);
    unsigned short ub = *reinterpret_cast<unsigned short*>(&b);
    return (u32)ua | ((u32)ub << 16);
}
__device__ __forceinline__ float gelu_exact(float v) {
    return 0.5f * v * (1.f + erff(v * 0.70710678118654752f));
}

// ---------------------------------------------------------------------------
__global__ void zero_kernel(float* __restrict__ out) {
    size_t n4 = (size_t)T_TOK * D_DIM / 4;
    size_t i  = (size_t)blockIdx.x * blockDim.x + threadIdx.x;
    float4 z = make_float4(0.f, 0.f, 0.f, 0.f);
    for (; i < n4; i += (size_t)gridDim.x * blockDim.x)
        reinterpret_cast<float4*>(out)[i] = z;
    if (blockIdx.x == 0 && threadIdx.x < NE) {
        g_cnt[threadIdx.x] = 0;
        g_imp[threadIdx.x] = 0.f;
    }
}

// x fp32 -> fp16 hi/lo planes
__global__ void xsplit_kernel(const float* __restrict__ x) {
    size_t i = (size_t)blockIdx.x * blockDim.x + threadIdx.x;
    float4 v = reinterpret_cast<const float4*>(x)[i];
    __half h0 = __float2half_rn(v.x), h1 = __float2half_rn(v.y);
    __half h2 = __float2half_rn(v.z), h3 = __float2half_rn(v.w);
    __half l0 = __float2half_rn(v.x - __half2float(h0));
    __half l1 = __float2half_rn(v.y - __half2float(h1));
    __half l2 = __float2half_rn(v.z - __half2float(h2));
    __half l3 = __float2half_rn(v.w - __half2float(h3));
    reinterpret_cast<uint2*>(g_xh)[i] = make_uint2(pack_h2(h0, h1), pack_h2(h2, h3));
    reinterpret_cast<uint2*>(g_xl)[i] = make_uint2(pack_h2(l0, l1), pack_h2(l2, l3));
}

// weight transpose + fp16 round: in[e][R][C] fp32 -> out[e][C][R] fp16
__global__ void convT_kernel(const float* __restrict__ in,
                             __half* __restrict__ o,
                             int R, int C)
{
    __shared__ float s[32][33];
    int e  = blockIdx.z;
    int c0 = blockIdx.x * 32, r0 = blockIdx.y * 32;
    const float* ip = in + (size_t)e * R * C;
#pragma unroll
    for (int k = 0; k < 32; k += 8)
        s[threadIdx.y + k][threadIdx.x] =
            ip[(size_t)(r0 + threadIdx.y + k) * C + c0 + threadIdx.x];
    __syncthreads();
#pragma unroll
    for (int k = 0; k < 32; k += 8) {
        float v = s[threadIdx.x][threadIdx.y + k];
        size_t oo = ((size_t)e * C + c0 + threadIdx.y + k) * R + r0 + threadIdx.x;
        o[oo] = __float2half_rn(v);
    }
}

// ---------------------------------------------------------------------------
__global__ __launch_bounds__(256) void router_kernel(
    const float* __restrict__ x,
    const float* __restrict__ Wr,
    const float* __restrict__ br)
{
    __shared__ float sWr[D_DIM * NE];
    __shared__ float s_imp[NE];
    int tid = threadIdx.x;
    for (int i = tid; i < D_DIM * NE; i += 256) sWr[i] = Wr[i];
    if (tid < NE) s_imp[tid] = 0.f;
    __syncthreads();

    int warp = tid >> 5, lane = tid & 31;
    int t = blockIdx.x * 8 + warp;

    float acc[NE];
#pragma unroll
    for (int e = 0; e < NE; e++) acc[e] = 0.f;

    const float* xr = x + (size_t)t * D_DIM;
    for (int d = lane; d < D_DIM; d += 32) {
        float xv = xr[d];
#pragma unroll
        for (int e = 0; e < NE; e++) acc[e] += xv * sWr[d * NE + e];
    }
#pragma unroll
    for (int e = 0; e < NE; e++) {
#pragma unroll
        for (int off = 16; off > 0; off >>= 1)
            acc[e] += __shfl_down_sync(0xffffffffu, acc[e], off);
    }

    if (lane == 0) {
        float p[NE];
        float mx = -1e30f;
#pragma unroll
        for (int e = 0; e < NE; e++) { p[e] = acc[e] + br[e]; mx = fmaxf(mx, p[e]); }
        float s = 0.f;
#pragma unroll
        for (int e = 0; e < NE; e++) { p[e] = expf(p[e] - mx); s += p[e]; }
        float inv = 1.f / s;
#pragma unroll
        for (int e = 0; e < NE; e++) {
            p[e] *= inv;
            atomicAdd(&s_imp[e], p[e]);
        }
        int i0 = 0;
#pragma unroll
        for (int e = 1; e < NE; e++) if (p[e] > p[i0]) i0 = e;
        int i1 = -1;
        float best1 = -1.f;
#pragma unroll
        for (int e = 0; e < NE; e++) {
            if (e == i0) continue;
            if (p[e] > best1) { best1 = p[e]; i1 = e; }
        }
        float w0 = p[i0], w1 = p[i1];
        float ws = fmaxf(w0 + w1, 1e-9f);
        w0 /= ws; w1 /= ws;

        int s0 = atomicAdd(&g_cnt[i0], 1);
        g_btok[i0 * T_TOK + s0] = t;
        g_bw[i0 * T_TOK + s0]   = w0;
        int s1 = atomicAdd(&g_cnt[i1], 1);
        g_btok[i1 * T_TOK + s1] = t;
        g_bw[i1 * T_TOK + s1]   = w1;
    }
    __syncthreads();
    if (tid < NE) atomicAdd(&g_imp[tid], s_imp[tid]);
}

// ---------------------------------------------------------------------------
// GEMM1: (xh + xl) @ W1 fp16, both terms f32-acc into one accumulator
// ---------------------------------------------------------------------------
__global__ __launch_bounds__(256) void gemm1_mma(const float* __restrict__ b1)
{
    int e    = blockIdx.z;
    int cnt  = g_cnt[e];
    int row0 = blockIdx.y * 128;
    if (row0 >= cnt) return;
    int n0 = blockIdx.x * 128;

    extern __shared__ char smem[];
    float* sBias = (float*)smem;
    int*   stok  = (int*)(smem + 512);
    u32 tb = cvta_smem(smem + 1024);

    int tid = threadIdx.x, lane = tid & 31, wid = tid >> 5;
    if (tid < 128) {
        sBias[tid] = b1[e * H_DIM + n0 + tid];
        int r = row0 + tid;
        stok[tid] = (r < cnt) ? g_btok[e * T_TOK + r] : 0;
    }
    __syncthreads();

    const __half* Bp = g_w1 + ((size_t)e * H_DIM + n0) * D_DIM;

    const int NCH = D_DIM / CH;   // 32
    auto issue = [&](int it, int s) {
        int k0 = it * CH;
        u32 base = tb + s * STG_BYTES;
#pragma unroll
        for (int t = 0; t < 2; t++) {
            int idx = t * 256 + tid;
            int row = idx >> 2, c = idx & 3;
            u32 so = swz64((row << 6) + (c << 4));
            size_t aoff = (size_t)stok[row] * D_DIM + k0 + c * 8;
            cp16(base + so,         g_xh + aoff);
            cp16(base + 8192 + so,  g_xl + aoff);
            cp16(base + 16384 + so, Bp + (size_t)row * D_DIM + k0 + c * 8);
        }
        cp_commit();
    };
    issue(0, 0); issue(1, 1); issue(2, 2);

    float accF[4][4][4];
#pragma unroll
    for (int i = 0; i < 4; i++)
#pragma unroll
        for (int j = 0; j < 4; j++)
#pragma unroll
            for (int k = 0; k < 4; k++) accF[i][j][k] = 0.f;

    int wm = wid & 1, wn = wid >> 1;

    for (int it = 0; it < NCH; ++it) {
        asm volatile("cp.async.wait_group 2;" ::: "memory");
        __syncthreads();
        if (it + 3 < NCH) issue(it + 3, (it + 3) % STAGES);
        u32 base = tb + (it % STAGES) * STG_BYTES;
#pragma unroll
        for (int ks = 0; ks < 2; ++ks) {
            u32 ah[4][4], al[4][4], b[2][4];
            int kby = ks * 32 + (lane >> 4) * 16;
#pragma unroll
            for (int mf = 0; mf < 4; ++mf) {
                int rr = wm * 64 + mf * 16 + (lane & 15);
                u32 off = swz64((rr << 6) + kby);
                ldsm4(ah[mf][0], ah[mf][1], ah[mf][2], ah[mf][3], base + off);
                ldsm4(al[mf][0], al[mf][1], al[mf][2], al[mf][3], base + 8192 + off);
            }
#pragma unroll
            for (int g = 0; g < 2; ++g) {
                int rr = wn * 32 + g * 16 + (lane & 15);
                u32 off = swz64((rr << 6) + kby);
                ldsm4(b[g][0], b[g][1], b[g][2], b[g][3], base + 16384 + off);
            }
#pragma unroll
            for (int mf = 0; mf < 4; ++mf)
#pragma unroll
                for (int nf = 0; nf < 4; ++nf) {
                    int g = nf >> 1, h = nf & 1;
                    mma_f32(accF[mf][nf], ah[mf], b[g][h], b[g][2 + h]);
                }
#pragma unroll
            for (int mf = 0; mf < 4; ++mf)
#pragma unroll
                for (int nf = 0; nf < 4; ++nf) {
                    int g = nf >> 1, h = nf & 1;
                    mma_f32(accF[mf][nf], al[mf], b[g][h], b[g][2 + h]);
                }
        }
    }

    // epilogue: bias + gelu + fp16 split
#pragma unroll
    for (int mf = 0; mf < 4; ++mf) {
        int rb = row0 + wm * 64 + mf * 16 + (lane >> 2);
#pragma unroll
        for (int half = 0; half < 2; ++half) {
            int r = rb + half * 8;
            if (r < cnt) {
                size_t rowoff = ((size_t)e * T_TOK + r) * H_DIM;
#pragma unroll
                for (int nf = 0; nf < 4; ++nf) {
                    int cl = wn * 32 + nf * 8 + (lane & 3) * 2;
                    float v0 = gelu_exact(accF[mf][nf][half * 2 + 0] + sBias[cl]);
                    float v1 = gelu_exact(accF[mf][nf][half * 2 + 1] + sBias[cl + 1]);
                    __half h0 = __float2half_rn(v0), h1 = __float2half_rn(v1);
                    __half l0 = __float2half_rn(v0 - __half2float(h0));
                    __half l1 = __float2half_rn(v1 - __half2float(h1));
                    *reinterpret_cast<u32*>(g_hh + rowoff + n0 + cl) = pack_h2(h0, h1);
                    *reinterpret_cast<u32*>(g_hl + rowoff + n0 + cl) = pack_h2(l0, l1);
                }
            }
        }
    }
}

// ---------------------------------------------------------------------------
// GEMM2: (hh + hl) @ W2 fp16; weighted atomic combine
// ---------------------------------------------------------------------------
__global__ __launch_bounds__(256) void gemm2_mma(const float* __restrict__ b2,
                                                 float* __restrict__ out)
{
    int e    = blockIdx.z;
    int cnt  = g_cnt[e];
    int row0 = blockIdx.y * 128;
    if (row0 >= cnt) return;
    int n0 = blockIdx.x * 128;

    extern __shared__ char smem[];
    float* sBias = (float*)smem;
    u32 tb = cvta_smem(smem + 1024);

    int tid = threadIdx.x, lane = tid & 31, wid = tid >> 5;
    if (tid < 128) sBias[tid] = b2[e * D_DIM + n0 + tid];
    __syncthreads();

    const __half* Ah = g_hh + (size_t)e * T_TOK * H_DIM;
    const __half* Al = g_hl + (size_t)e * T_TOK * H_DIM;
    const __half* Bp = g_w2 + ((size_t)e * D_DIM + n0) * H_DIM;

    const int NCH = H_DIM / CH;   // 64
    auto issue = [&](int it, int s) {
        int k0 = it * CH;
        u32 base = tb + s * STG_BYTES;
#pragma unroll
        for (int t = 0; t < 2; t++) {
            int idx = t * 256 + tid;
            int row = idx >> 2, c = idx & 3;
            int rr = row0 + row;
            if (rr >= cnt) rr = cnt - 1;
            u32 so = swz64((row << 6) + (c << 4));
            size_t aoff = (size_t)rr * H_DIM + k0 + c * 8;
            cp16(base + so,         Ah + aoff);
            cp16(base + 8192 + so,  Al + aoff);
            cp16(base + 16384 + so, Bp + (size_t)row * H_DIM + k0 + c * 8);
        }
        cp_commit();
    };
    issue(0, 0); issue(1, 1); issue(2, 2);

    float accF[4][4][4];
#pragma unroll
    for (int i = 0; i < 4; i++)
#pragma unroll
        for (int j = 0; j < 4; j++)
#pragma unroll
            for (int k = 0; k < 4; k++) accF[i][j][k] = 0.f;

    int wm = wid & 1, wn = wid >> 1;

    for (int it = 0; it < NCH; ++it) {
        asm volatile("cp.async.wait_group 2;" ::: "memory");
        __syncthreads();
        if (it + 3 < NCH) issue(it + 3, (it + 3) % STAGES);
        u32 base = tb + (it % STAGES) * STG_BYTES;
#pragma unroll
        for (int ks = 0; ks < 2; ++ks) {
            u32 ah[4][4], al[4][4], b[2][4];
            int kby = ks * 32 + (lane >> 4) * 16;
#pragma unroll
            for (int mf = 0; mf < 4; ++mf) {
                int rr = wm * 64 + mf * 16 + (lane & 15);
                u32 off = swz64((rr << 6) + kby);
                ldsm4(ah[mf][0], ah[mf][1], ah[mf][2], ah[mf][3], base + off);
                ldsm4(al[mf][0], al[mf][1], al[mf][2], al[mf][3], base + 8192 + off);
            }
#pragma unroll
            for (int g = 0; g < 2; ++g) {
                int rr = wn * 32 + g * 16 + (lane & 15);
                u32 off = swz64((rr << 6) + kby);
                ldsm4(b[g][0], b[g][1], b[g][2], b[g][3], base + 16384 + off);
            }
#pragma unroll
            for (int mf = 0; mf < 4; ++mf)
#pragma unroll
                for (int nf = 0; nf < 4; ++nf) {
                    int g = nf >> 1, h = nf & 1;
                    mma_f32(accF[mf][nf], ah[mf], b[g][h], b[g][2 + h]);
                }
#pragma unroll
            for (int mf = 0; mf < 4; ++mf)
#pragma unroll
                for (int nf = 0; nf < 4; ++nf) {
                    int g = nf >> 1, h = nf & 1;
                    mma_f32(accF[mf][nf], al[mf], b[g][h], b[g][2 + h]);
                }
        }
    }

    // epilogue: out[tok] += w * (y + b2)
#pragma unroll
    for (int mf = 0; mf < 4; ++mf) {
        int rb = row0 + wm * 64 + mf * 16 + (lane >> 2);
#pragma unroll
        for (int half = 0; half < 2; ++half) {
            int r = rb + half * 8;
            if (r < cnt) {
                int   tok = g_btok[e * T_TOK + r];
                float w   = g_bw[e * T_TOK + r];
                float* orow = out + (size_t)tok * D_DIM + n0;
#pragma unroll
                for (int nf = 0; nf < 4; ++nf) {
                    int cl = wn * 32 + nf * 8 + (lane & 3) * 2;
                    atomicAdd(orow + cl,
                              w * (accF[mf][nf][half * 2 + 0] + sBias[cl]));
                    atomicAdd(orow + cl + 1,
                              w * (accF[mf][nf][half * 2 + 1] + sBias[cl + 1]));
                }
            }
        }
    }
}

// ---------------------------------------------------------------------------
__global__ void finalize_kernel(float* __restrict__ out) {
    int tot = 0;
#pragma unroll
    for (int e = 0; e < NE; e++) tot += g_cnt[e];
    float denom = fmaxf((float)tot, 1.f);
    float s = 0.f;
#pragma unroll
    for (int e = 0; e < NE; e++)
        s += (g_imp[e] / (float)T_TOK) * ((float)g_cnt[e] / denom);
    out[(size_t)T_TOK * D_DIM] = (float)NE * s;
}

// ---------------------------------------------------------------------------
extern "C" void kernel_launch(void* const* d_in, const int* in_sizes, int n_in,
                              void* d_out, int out_size)
{
    const float* x  = (const float*)d_in[0];
    const float* Wr = (const float*)d_in[1];
    const float* br = (const float*)d_in[2];
    const float* W1 = (const float*)d_in[3];
    const float* b1 = (const float*)d_in[4];
    const float* W2 = (const float*)d_in[5];
    const float* b2 = (const float*)d_in[6];
    float* out = (float*)d_out;

    cudaFuncSetAttribute(gemm1_mma, cudaFuncAttributeMaxDynamicSharedMemorySize, SMEM_BYTES);
    cudaFuncSetAttribute(gemm2_mma, cudaFuncAttributeMaxDynamicSharedMemorySize, SMEM_BYTES);

    __half *w1, *w2;
    cudaGetSymbolAddress((void**)&w1, g_w1);
    cudaGetSymbolAddress((void**)&w2, g_w2);

    zero_kernel<<<2048, 512>>>(out);
    xsplit_kernel<<<(T_TOK * D_DIM / 4) / 512, 512>>>(x);
    convT_kernel<<<dim3(H_DIM / 32, D_DIM / 32, NE), dim3(32, 8)>>>(W1, w1, D_DIM, H_DIM);
    convT_kernel<<<dim3(D_DIM / 32, H_DIM / 32, NE), dim3(32, 8)>>>(W2, w2, H_DIM, D_DIM);
    router_kernel<<<T_TOK / 8, 256>>>(x, Wr, br);
    gemm1_mma<<<dim3(H_DIM / 128, T_TOK / 128, NE), 256, SMEM_BYTES>>>(b1);
    gemm2_mma<<<dim3(D_DIM / 128, T_TOK / 128, NE), 256, SMEM_BYTES>>>(b2, out);
    if (out_size > T_TOK * D_DIM)
        finalize_kernel<<<1, 1>>>(out);
}

// round 6
// speedup vs baseline: 6.0760x; 1.9013x over previous
#include <cuda_runtime.h>
#include <cuda_fp16.h>
#include <math.h>

#define T_TOK 8192
#define D_DIM 1024
#define H_DIM 2048
#define NE    8
#define CH    32
#define STAGES 5
#define STG_BYTES 16384
#define SMEM_BYTES (1024 + STAGES * STG_BYTES)

typedef unsigned int u32;
typedef unsigned long long u64;

// ---------------- static device scratch ----------------
__device__ int   g_cnt[NE];
__device__ float g_imp[NE];
__device__ int   g_btok[NE * T_TOK];
__device__ float g_bw[NE * T_TOK];
__device__ __half g_x16[(size_t)T_TOK * D_DIM];
__device__ __half g_w1[(size_t)NE * H_DIM * D_DIM];    // W1^T fp16 [e][h][d]
__device__ __half g_w2[(size_t)NE * D_DIM * H_DIM];    // W2^T fp16 [e][d][h]
__device__ __half g_h[(size_t)NE * T_TOK * H_DIM];     // hidden fp16

// ---------------- helpers ----------------
__device__ __forceinline__ u32 cvta_smem(const void* p) {
    u32 a;
    asm("{ .reg .u64 t; cvta.to.shared.u64 t, %1; cvt.u32.u64 %0, t; }" : "=r"(a) : "l"(p));
    return a;
}
__device__ __forceinline__ void cp16(u32 dst, const void* src) {
    asm volatile("cp.async.cg.shared.global [%0], [%1], 16;" :: "r"(dst), "l"(src));
}
__device__ __forceinline__ void cp_commit() { asm volatile("cp.async.commit_group;"); }
__device__ __forceinline__ void ldsm4(u32& r0, u32& r1, u32& r2, u32& r3, u32 addr) {
    asm volatile("ldmatrix.sync.aligned.m8n8.x4.shared.b16 {%0,%1,%2,%3}, [%4];"
                 : "=r"(r0), "=r"(r1), "=r"(r2), "=r"(r3) : "r"(addr));
}
__device__ __forceinline__ void mma_f32(float* c, const u32* a, u32 b0, u32 b1) {
    asm volatile("mma.sync.aligned.m16n8k16.row.col.f32.f16.f16.f32 "
                 "{%0,%1,%2,%3}, {%4,%5,%6,%7}, {%8,%9}, {%0,%1,%2,%3};"
                 : "+f"(c[0]), "+f"(c[1]), "+f"(c[2]), "+f"(c[3])
                 : "r"(a[0]), "r"(a[1]), "r"(a[2]), "r"(a[3]), "r"(b0), "r"(b1));
}
// 64B-row swizzle
__device__ __forceinline__ u32 swz64(u32 o) { return o ^ ((o >> 3) & 0x30); }
__device__ __forceinline__ u32 pack_h2(__half a, __half b) {
    unsigned short ua = *reinterpret_cast<unsigned short*>(&a);
    unsigned short ub = *reinterpret_cast<unsigned short*>(&b);
    return (u32)ua | ((u32)ub << 16);
}
__device__ __forceinline__ float gelu_exact(float v) {
    return 0.5f * v * (1.f + erff(v * 0.70710678118654752f));
}

// ---------------------------------------------------------------------------
__global__ void zero_kernel(float* __restrict__ out) {
    size_t n4 = (size_t)T_TOK * D_DIM / 4;
    size_t i  = (size_t)blockIdx.x * blockDim.x + threadIdx.x;
    float4 z = make_float4(0.f, 0.f, 0.f, 0.f);
    for (; i < n4; i += (size_t)gridDim.x * blockDim.x)
        reinterpret_cast<float4*>(out)[i] = z;
    if (blockIdx.x == 0 && threadIdx.x < NE) {
        g_cnt[threadIdx.x] = 0;
        g_imp[threadIdx.x] = 0.f;
    }
}

// x fp32 -> fp16
__global__ void xcvt_kernel(const float* __restrict__ x) {
    size_t i = (size_t)blockIdx.x * blockDim.x + threadIdx.x;
    float4 v = reinterpret_cast<const float4*>(x)[i];
    reinterpret_cast<uint2*>(g_x16)[i] =
        make_uint2(pack_h2(__float2half_rn(v.x), __float2half_rn(v.y)),
                   pack_h2(__float2half_rn(v.z), __float2half_rn(v.w)));
}

// weight transpose + fp16 round: in[e][R][C] fp32 -> out[e][C][R] fp16
__global__ void convT_kernel(const float* __restrict__ in,
                             __half* __restrict__ o,
                             int R, int C)
{
    __shared__ float s[32][33];
    int e  = blockIdx.z;
    int c0 = blockIdx.x * 32, r0 = blockIdx.y * 32;
    const float* ip = in + (size_t)e * R * C;
#pragma unroll
    for (int k = 0; k < 32; k += 8)
        s[threadIdx.y + k][threadIdx.x] =
            ip[(size_t)(r0 + threadIdx.y + k) * C + c0 + threadIdx.x];
    __syncthreads();
#pragma unroll
    for (int k = 0; k < 32; k += 8) {
        float v = s[threadIdx.x][threadIdx.y + k];
        size_t oo = ((size_t)e * C + c0 + threadIdx.y + k) * R + r0 + threadIdx.x;
        o[oo] = __float2half_rn(v);
    }
}

// ---------------------------------------------------------------------------
__global__ __launch_bounds__(256) void router_kernel(
    const float* __restrict__ x,
    const float* __restrict__ Wr,
    const float* __restrict__ br)
{
    __shared__ float sWr[D_DIM * NE];
    __shared__ float s_imp[NE];
    int tid = threadIdx.x;
    for (int i = tid; i < D_DIM * NE; i += 256) sWr[i] = Wr[i];
    if (tid < NE) s_imp[tid] = 0.f;
    __syncthreads();

    int warp = tid >> 5, lane = tid & 31;
    int t = blockIdx.x * 8 + warp;

    float acc[NE];
#pragma unroll
    for (int e = 0; e < NE; e++) acc[e] = 0.f;

    const float* xr = x + (size_t)t * D_DIM;
    for (int d = lane; d < D_DIM; d += 32) {
        float xv = xr[d];
#pragma unroll
        for (int e = 0; e < NE; e++) acc[e] += xv * sWr[d * NE + e];
    }
#pragma unroll
    for (int e = 0; e < NE; e++) {
#pragma unroll
        for (int off = 16; off > 0; off >>= 1)
            acc[e] += __shfl_down_sync(0xffffffffu, acc[e], off);
    }

    if (lane == 0) {
        float p[NE];
        float mx = -1e30f;
#pragma unroll
        for (int e = 0; e < NE; e++) { p[e] = acc[e] + br[e]; mx = fmaxf(mx, p[e]); }
        float s = 0.f;
#pragma unroll
        for (int e = 0; e < NE; e++) { p[e] = expf(p[e] - mx); s += p[e]; }
        float inv = 1.f / s;
#pragma unroll
        for (int e = 0; e < NE; e++) {
            p[e] *= inv;
            atomicAdd(&s_imp[e], p[e]);
        }
        int i0 = 0;
#pragma unroll
        for (int e = 1; e < NE; e++) if (p[e] > p[i0]) i0 = e;
        int i1 = -1;
        float best1 = -1.f;
#pragma unroll
        for (int e = 0; e < NE; e++) {
            if (e == i0) continue;
            if (p[e] > best1) { best1 = p[e]; i1 = e; }
        }
        float w0 = p[i0], w1 = p[i1];
        float ws = fmaxf(w0 + w1, 1e-9f);
        w0 /= ws; w1 /= ws;

        int s0 = atomicAdd(&g_cnt[i0], 1);
        g_btok[i0 * T_TOK + s0] = t;
        g_bw[i0 * T_TOK + s0]   = w0;
        int s1 = atomicAdd(&g_cnt[i1], 1);
        g_btok[i1 * T_TOK + s1] = t;
        g_bw[i1 * T_TOK + s1]   = w1;
    }
    __syncthreads();
    if (tid < NE) atomicAdd(&g_imp[tid], s_imp[tid]);
}

// ---------------------------------------------------------------------------
// GEMM1: x16 @ W1 fp16, f32 acc -> gelu -> g_h
// ---------------------------------------------------------------------------
__global__ __launch_bounds__(256) void gemm1_mma(const float* __restrict__ b1)
{
    int e    = blockIdx.z;
    int cnt  = g_cnt[e];
    int row0 = blockIdx.y * 128;
    if (row0 >= cnt) return;
    int n0 = blockIdx.x * 128;

    extern __shared__ char smem[];
    float* sBias = (float*)smem;
    int*   stok  = (int*)(smem + 512);
    u32 tb = cvta_smem(smem + 1024);

    int tid = threadIdx.x, lane = tid & 31, wid = tid >> 5;
    if (tid < 128) {
        sBias[tid] = b1[e * H_DIM + n0 + tid];
        int r = row0 + tid;
        stok[tid] = (r < cnt) ? g_btok[e * T_TOK + r] : 0;
    }
    __syncthreads();

    const __half* Bp = g_w1 + ((size_t)e * H_DIM + n0) * D_DIM;

    const int NCH = D_DIM / CH;   // 32
    auto issue = [&](int it, int s) {
        int k0 = it * CH;
        u32 base = tb + s * STG_BYTES;
#pragma unroll
        for (int t = 0; t < 2; t++) {
            int idx = t * 256 + tid;
            int row = idx >> 2, c = idx & 3;
            u32 so = swz64((row << 6) + (c << 4));
            cp16(base + so,        g_x16 + (size_t)stok[row] * D_DIM + k0 + c * 8);
            cp16(base + 8192 + so, Bp + (size_t)row * D_DIM + k0 + c * 8);
        }
        cp_commit();
    };
    issue(0, 0); issue(1, 1); issue(2, 2);

    float accF[4][4][4];
#pragma unroll
    for (int i = 0; i < 4; i++)
#pragma unroll
        for (int j = 0; j < 4; j++)
#pragma unroll
            for (int k = 0; k < 4; k++) accF[i][j][k] = 0.f;

    int wm = wid & 1, wn = wid >> 1;

    for (int it = 0; it < NCH; ++it) {
        asm volatile("cp.async.wait_group 2;" ::: "memory");
        __syncthreads();
        if (it + 3 < NCH) issue(it + 3, (it + 3) % STAGES);
        u32 base = tb + (it % STAGES) * STG_BYTES;
#pragma unroll
        for (int ks = 0; ks < 2; ++ks) {
            u32 a[4][4], b[2][4];
            int kby = ks * 32 + (lane >> 4) * 16;
#pragma unroll
            for (int mf = 0; mf < 4; ++mf) {
                int rr = wm * 64 + mf * 16 + (lane & 15);
                ldsm4(a[mf][0], a[mf][1], a[mf][2], a[mf][3], base + swz64((rr << 6) + kby));
            }
#pragma unroll
            for (int g = 0; g < 2; ++g) {
                int rr = wn * 32 + g * 16 + (lane & 15);
                ldsm4(b[g][0], b[g][1], b[g][2], b[g][3], base + 8192 + swz64((rr << 6) + kby));
            }
#pragma unroll
            for (int mf = 0; mf < 4; ++mf)
#pragma unroll
                for (int nf = 0; nf < 4; ++nf) {
                    int g = nf >> 1, h = nf & 1;
                    mma_f32(accF[mf][nf], a[mf], b[g][h], b[g][2 + h]);
                }
        }
    }

    // epilogue: bias + gelu -> fp16
#pragma unroll
    for (int mf = 0; mf < 4; ++mf) {
        int rb = row0 + wm * 64 + mf * 16 + (lane >> 2);
#pragma unroll
        for (int half = 0; half < 2; ++half) {
            int r = rb + half * 8;
            if (r < cnt) {
                size_t rowoff = ((size_t)e * T_TOK + r) * H_DIM;
#pragma unroll
                for (int nf = 0; nf < 4; ++nf) {
                    int cl = wn * 32 + nf * 8 + (lane & 3) * 2;
                    float v0 = gelu_exact(accF[mf][nf][half * 2 + 0] + sBias[cl]);
                    float v1 = gelu_exact(accF[mf][nf][half * 2 + 1] + sBias[cl + 1]);
                    *reinterpret_cast<u32*>(g_h + rowoff + n0 + cl) =
                        pack_h2(__float2half_rn(v0), __float2half_rn(v1));
                }
            }
        }
    }
}

// ---------------------------------------------------------------------------
// GEMM2: h @ W2 fp16; weighted atomic combine
// ---------------------------------------------------------------------------
__global__ __launch_bounds__(256) void gemm2_mma(const float* __restrict__ b2,
                                                 float* __restrict__ out)
{
    int e    = blockIdx.z;
    int cnt  = g_cnt[e];
    int row0 = blockIdx.y * 128;
    if (row0 >= cnt) return;
    int n0 = blockIdx.x * 128;

    extern __shared__ char smem[];
    float* sBias = (float*)smem;
    u32 tb = cvta_smem(smem + 1024);

    int tid = threadIdx.x, lane = tid & 31, wid = tid >> 5;
    if (tid < 128) sBias[tid] = b2[e * D_DIM + n0 + tid];
    __syncthreads();

    const __half* Ap = g_h + (size_t)e * T_TOK * H_DIM;
    const __half* Bp = g_w2 + ((size_t)e * D_DIM + n0) * H_DIM;

    const int NCH = H_DIM / CH;   // 64
    auto issue = [&](int it, int s) {
        int k0 = it * CH;
        u32 base = tb + s * STG_BYTES;
#pragma unroll
        for (int t = 0; t < 2; t++) {
            int idx = t * 256 + tid;
            int row = idx >> 2, c = idx & 3;
            int rr = row0 + row;
            if (rr >= cnt) rr = cnt - 1;
            u32 so = swz64((row << 6) + (c << 4));
            cp16(base + so,        Ap + (size_t)rr * H_DIM + k0 + c * 8);
            cp16(base + 8192 + so, Bp + (size_t)row * H_DIM + k0 + c * 8);
        }
        cp_commit();
    };
    issue(0, 0); issue(1, 1); issue(2, 2);

    float accF[4][4][4];
#pragma unroll
    for (int i = 0; i < 4; i++)
#pragma unroll
        for (int j = 0; j < 4; j++)
#pragma unroll
            for (int k = 0; k < 4; k++) accF[i][j][k] = 0.f;

    int wm = wid & 1, wn = wid >> 1;

    for (int it = 0; it < NCH; ++it) {
        asm volatile("cp.async.wait_group 2;" ::: "memory");
        __syncthreads();
        if (it + 3 < NCH) issue(it + 3, (it + 3) % STAGES);
        u32 base = tb + (it % STAGES) * STG_BYTES;
#pragma unroll
        for (int ks = 0; ks < 2; ++ks) {
            u32 a[4][4], b[2][4];
            int kby = ks * 32 + (lane >> 4) * 16;
#pragma unroll
            for (int mf = 0; mf < 4; ++mf) {
                int rr = wm * 64 + mf * 16 + (lane & 15);
                ldsm4(a[mf][0], a[mf][1], a[mf][2], a[mf][3], base + swz64((rr << 6) + kby));
            }
#pragma unroll
            for (int g = 0; g < 2; ++g) {
                int rr = wn * 32 + g * 16 + (lane & 15);
                ldsm4(b[g][0], b[g][1], b[g][2], b[g][3], base + 8192 + swz64((rr << 6) + kby));
            }
#pragma unroll
            for (int mf = 0; mf < 4; ++mf)
#pragma unroll
                for (int nf = 0; nf < 4; ++nf) {
                    int g = nf >> 1, h = nf & 1;
                    mma_f32(accF[mf][nf], a[mf], b[g][h], b[g][2 + h]);
                }
        }
    }

    // epilogue: out[tok] += w * (y + b2)
#pragma unroll
    for (int mf = 0; mf < 4; ++mf) {
        int rb = row0 + wm * 64 + mf * 16 + (lane >> 2);
#pragma unroll
        for (int half = 0; half < 2; ++half) {
            int r = rb + half * 8;
            if (r < cnt) {
                int   tok = g_btok[e * T_TOK + r];
                float w   = g_bw[e * T_TOK + r];
                float* orow = out + (size_t)tok * D_DIM + n0;
#pragma unroll
                for (int nf = 0; nf < 4; ++nf) {
                    int cl = wn * 32 + nf * 8 + (lane & 3) * 2;
                    atomicAdd(orow + cl,
                              w * (accF[mf][nf][half * 2 + 0] + sBias[cl]));
                    atomicAdd(orow + cl + 1,
                              w * (accF[mf][nf][half * 2 + 1] + sBias[cl + 1]));
                }
            }
        }
    }
}

// ---------------------------------------------------------------------------
__global__ void finalize_kernel(float* __restrict__ out) {
    int tot = 0;
#pragma unroll
    for (int e = 0; e < NE; e++) tot += g_cnt[e];
    float denom = fmaxf((float)tot, 1.f);
    float s = 0.f;
#pragma unroll
    for (int e = 0; e < NE; e++)
        s += (g_imp[e] / (float)T_TOK) * ((float)g_cnt[e] / denom);
    out[(size_t)T_TOK * D_DIM] = (float)NE * s;
}

// ---------------------------------------------------------------------------
extern "C" void kernel_launch(void* const* d_in, const int* in_sizes, int n_in,
                              void* d_out, int out_size)
{
    const float* x  = (const float*)d_in[0];
    const float* Wr = (const float*)d_in[1];
    const float* br = (const float*)d_in[2];
    const float* W1 = (const float*)d_in[3];
    const float* b1 = (const float*)d_in[4];
    const float* W2 = (const float*)d_in[5];
    const float* b2 = (const float*)d_in[6];
    float* out = (float*)d_out;

    cudaFuncSetAttribute(gemm1_mma, cudaFuncAttributeMaxDynamicSharedMemorySize, SMEM_BYTES);
    cudaFuncSetAttribute(gemm2_mma, cudaFuncAttributeMaxDynamicSharedMemorySize, SMEM_BYTES);

    __half *w1, *w2;
    cudaGetSymbolAddress((void**)&w1, g_w1);
    cudaGetSymbolAddress((void**)&w2, g_w2);

    zero_kernel<<<2048, 512>>>(out);
    xcvt_kernel<<<(T_TOK * D_DIM / 4) / 512, 512>>>(x);
    convT_kernel<<<dim3(H_DIM / 32, D_DIM / 32, NE), dim3(32, 8)>>>(W1, w1, D_DIM, H_DIM);
    convT_kernel<<<dim3(D_DIM / 32, H_DIM / 32, NE), dim3(32, 8)>>>(W2, w2, H_DIM, D_DIM);
    router_kernel<<<T_TOK / 8, 256>>>(x, Wr, br);
    gemm1_mma<<<dim3(H_DIM / 128, T_TOK / 128, NE), 256, SMEM_BYTES>>>(b1);
    gemm2_mma<<<dim3(D_DIM / 128, T_TOK / 128, NE), 256, SMEM_BYTES>>>(b2, out);
    if (out_size > T_TOK * D_DIM)
        finalize_kernel<<<1, 1>>>(out);
}